// round 10
// baseline (speedup 1.0000x reference)
#include <cuda_runtime.h>
#include <cstdint>

#define H 128
#define W 128
#define NCONV 8
#define TILE_ROWS 8
#define FROWS 10          // TILE_ROWS + 2 halo
#define ESTRIDE 66        // entries per (f,row) in Pe/Po (65/64 used, padded)
#define XSTRIDE 132       // x-buffer floats per row (130 used, padded)
#define NTHREADS 256
#define NWARP 8
#define NTASK (FROWS * 5) // 50 feature tasks
#define NTILES 4096
#define GRID 592          // 148 SMs x 4 CTAs, persistent

// dynamic smem layout (bytes)
#define OFF_PE   0                                   // ull Pe[4][10][66] = 21120  (P[2m])
#define OFF_PO   21120                               // ull Po[4][10][66] = 21120  (P[2m+1])
#define OFF_W    42240                               // ull w[288]        = 2304
#define OFF_B    44544                               // ull bias[8]       = 64
#define OFF_XB   44608                               // float xb[10][132] = 5280
#define SMEM_BYTES 49888

typedef unsigned long long ull;

__device__ __forceinline__ ull pk2(float lo, float hi) {
    ull r; asm("mov.b64 %0, {%1, %2};" : "=l"(r) : "f"(lo), "f"(hi)); return r;
}
__device__ __forceinline__ void fma2(ull &d, ull a, ull b) {
    asm("fma.rn.f32x2 %0, %1, %2, %0;" : "+l"(d) : "l"(a), "l"(b));
}
__device__ __forceinline__ float tanh_ap(float x) {
    float r; asm("tanh.approx.f32 %0, %1;" : "=f"(r) : "f"(x)); return r;
}
__device__ __forceinline__ void cp_async4(uint32_t dst, const void* src, int srcsize) {
    asm volatile("cp.async.ca.shared.global [%0], [%1], 4, %2;"
                 :: "r"(dst), "l"(src), "r"(srcsize) : "memory");
}
__device__ __forceinline__ void cp_commit() {
    asm volatile("cp.async.commit_group;" ::: "memory");
}
__device__ __forceinline__ void cp_wait0() {
    asm volatile("cp.async.wait_group 0;" ::: "memory");
}

// features of one input value: 2 MUFU + a few fma
__device__ __forceinline__ void feats(float xv, float &s, float &t, float &t2, float &t3) {
    t = tanh_ap(xv);                               // tanh
    float th = tanh_ap(0.5f * xv);
    float sg = fmaf(0.5f, th, 0.5f);               // sigmoid(x)
    s  = xv * sg;                                  // silu
    t2 = fmaf(t + t, t, -1.f);                     // T2
    t3 = fmaf(t + t, t2, -t);                      // T3
}

// prefetch one tile's x (with zero halo) into the smem x-buffer via cp.async
__device__ __forceinline__ void prefetch_x(const float* __restrict__ x, int t,
                                           uint32_t xb_addr, int tid) {
    int bc = t >> 4;
    int r0 = (t & 15) * TILE_ROWS;
    const float* xp = x + (size_t)bc * (H * W);
    #pragma unroll
    for (int q = 0; q < 6; q++) {
        int idx = tid + q * NTHREADS;
        if (idx < FROWS * 130) {
            int row = idx / 130;
            int ii  = idx - row * 130;             // 0..129
            int col = ii - 1;                      // -1..128
            int gr  = r0 - 1 + row;
            bool v  = ((unsigned)gr < H) & ((unsigned)col < W);
            const float* src = v ? (xp + gr * W + col) : x;   // clamped addr, zfill
            cp_async4(xb_addr + (uint32_t)(row * XSTRIDE + ii) * 4, src, v ? 4 : 0);
        }
    }
    cp_commit();
}

__global__ void __launch_bounds__(NTHREADS, 4)
kan_conv_kernel(const float* __restrict__ x,
                const float* __restrict__ cheby,
                const float* __restrict__ bw,
                const float* __restrict__ ss,
                float* __restrict__ out)
{
    extern __shared__ char smem_raw[];
    ull*   Pe    = (ull*)  (smem_raw + OFF_PE);   // P[2m]   = (F(2m),   F(2m+1))
    ull*   Po    = (ull*)  (smem_raw + OFF_PO);   // P[2m+1] = (F(2m+1), F(2m+2))
    ull*   wsm   = (ull*)  (smem_raw + OFF_W);    // [(tap*4+f)*8 + j] dup pairs
    ull*   biasd = (ull*)  (smem_raw + OFF_B);
    float* xsm   = (float*)(smem_raw + OFF_XB);   // [row][ii], ii = col+1
    uint32_t xb_addr = (uint32_t)__cvta_generic_to_shared(xsm);

    const int tid  = threadIdx.x;
    const int wid  = tid >> 5;
    const int lane = tid & 31;

    // ---- once per CTA: weights -> smem (duplicated f32x2 pairs) ----
    for (int idx = tid; idx < 9 * 4 * 8; idx += NTHREADS) {
        int j   = idx & 7;
        int fi  = idx >> 3;
        int tap = fi >> 2;
        int f   = fi & 3;
        float wv;
        if (f == 0) wv = bw[j * 9 + tap];
        else        wv = cheby[(j * 9 + tap) * 4 + f] * ss[j * 9 + tap];
        wsm[idx] = pk2(wv, wv);
    }
    if (tid < NCONV) {
        float sum = 0.f;
        #pragma unroll
        for (int i = 0; i < 9; i++) sum += cheby[(tid * 9 + i) * 4] * ss[tid * 9 + i];
        biasd[tid] = pk2(sum, sum);
    }

    // ---- persistent tile loop with cross-tile cp.async pipeline ----
    prefetch_x(x, blockIdx.x, xb_addr, tid);

    for (int t = blockIdx.x; t < NTILES; t += GRID) {
        cp_wait0();
        __syncthreads();                           // xb ready; prev compute done

        // ---- Phase B: features xb -> parity-split pair smem, conflict-free ----
        #pragma unroll
        for (int q = 0; q < 7; q++) {
            int task = wid + q * NWARP;
            if (task < NTASK) {                    // warp-uniform predicate
                int row = task / 5;
                int c   = task - row * 5;
                int i   = c * 31 + lane;           // feature index (col = i-1)
                int ir  = i <= 129 ? i : 129;      // clamp read (stores guarded below)
                float xv = xsm[row * XSTRIDE + ir];
                float s, t1, t2, t3;
                feats(xv, s, t1, t2, t3);          // x=0 padding -> (0,0,-1,0) ✓
                float ps  = __shfl_up_sync(0xffffffffu, s,  1);
                float pt  = __shfl_up_sync(0xffffffffu, t1, 1);
                float pt2 = __shfl_up_sync(0xffffffffu, t2, 1);
                float pt3 = __shfl_up_sync(0xffffffffu, t3, 1);
                int k = i - 1;
                if (lane >= 1 && k <= 128) {
                    int m  = k >> 1;
                    int rb = row * ESTRIDE + m;
                    ull v0 = pk2(ps,  s);
                    ull v1 = pk2(pt,  t1);
                    ull v2 = pk2(pt2, t2);
                    ull v3 = pk2(pt3, t3);
                    if ((k & 1) == 0) {
                        Pe[(0 * FROWS) * ESTRIDE + rb] = v0;
                        Pe[(1 * FROWS) * ESTRIDE + rb] = v1;
                        Pe[(2 * FROWS) * ESTRIDE + rb] = v2;
                        Pe[(3 * FROWS) * ESTRIDE + rb] = v3;
                    } else {
                        Po[(0 * FROWS) * ESTRIDE + rb] = v0;
                        Po[(1 * FROWS) * ESTRIDE + rb] = v1;
                        Po[(2 * FROWS) * ESTRIDE + rb] = v2;
                        Po[(3 * FROWS) * ESTRIDE + rb] = v3;
                    }
                }
            }
        }
        __syncthreads();                           // Pe/Po ready; xb free

        // issue next tile's x prefetch — covered by the compute below
        int tn = t + GRID;
        if (tn < NTILES) prefetch_x(x, tn, xb_addr, tid);

        // ---- Compute: thread -> 2 out rows (ty, ty+1), cols {2L, 2L+1}, 8 j ----
        const int L  = tid & 63;                   // col-pair index, c0 = 2L
        const int ty = (tid >> 6) * 2;             // local out rows ty, ty+1

        ull acc[8][2];                             // [j][r]
        #pragma unroll
        for (int j = 0; j < 8; j++) {
            ull b = biasd[j];
            acc[j][0] = b; acc[j][1] = b;
        }

        #pragma unroll
        for (int f = 0; f < 4; f++) {
            ull lo[3], hi[3];
            {   // input rows ty (lo) and ty+1 (hi)
                int b0 = (f * FROWS + ty) * ESTRIDE + L;
                lo[0] = Pe[b0]; lo[1] = Po[b0]; lo[2] = Pe[b0 + 1];
                int b1 = b0 + ESTRIDE;
                hi[0] = Pe[b1]; hi[1] = Po[b1]; hi[2] = Pe[b1 + 1];
            }
            #pragma unroll
            for (int dy = 0; dy < 3; dy++) {
                #pragma unroll
                for (int dx = 0; dx < 3; dx++) {
                    const ulonglong2* wp = (const ulonglong2*)&wsm[((dy * 3 + dx) * 4 + f) * 8];
                    ull f0 = lo[dx];               // feeds out row ty
                    ull f1 = hi[dx];               // feeds out row ty+1
                    {   // j 0..3
                        ulonglong2 w01 = wp[0], w23 = wp[1];
                        fma2(acc[0][0], f0, w01.x); fma2(acc[0][1], f1, w01.x);
                        fma2(acc[1][0], f0, w01.y); fma2(acc[1][1], f1, w01.y);
                        fma2(acc[2][0], f0, w23.x); fma2(acc[2][1], f1, w23.x);
                        fma2(acc[3][0], f0, w23.y); fma2(acc[3][1], f1, w23.y);
                    }
                    {   // j 4..7
                        ulonglong2 w45 = wp[2], w67 = wp[3];
                        fma2(acc[4][0], f0, w45.x); fma2(acc[4][1], f1, w45.x);
                        fma2(acc[5][0], f0, w45.y); fma2(acc[5][1], f1, w45.y);
                        fma2(acc[6][0], f0, w67.x); fma2(acc[6][1], f1, w67.x);
                        fma2(acc[7][0], f0, w67.y); fma2(acc[7][1], f1, w67.y);
                    }
                }
                if (dy < 2) {                      // roll window
                    lo[0] = hi[0]; lo[1] = hi[1]; lo[2] = hi[2];
                    int bn = (f * FROWS + ty + dy + 2) * ESTRIDE + L;
                    hi[0] = Pe[bn]; hi[1] = Po[bn]; hi[2] = Pe[bn + 1];
                }
            }
        }

        // ---- stores: STG.64, dense per warp ----
        int bc = t >> 4;
        int r0 = (t & 15) * TILE_ROWS;
        float* ob = out + ((size_t)(bc * NCONV) * H + (r0 + ty)) * W + 2 * L;
        #pragma unroll
        for (int j = 0; j < 8; j++) {
            #pragma unroll
            for (int r = 0; r < 2; r++) {
                *(ull*)(ob + (size_t)j * (H * W) + r * W) = acc[j][r];
            }
        }
    }
}

extern "C" void kernel_launch(void* const* d_in, const int* in_sizes, int n_in,
                              void* d_out, int out_size) {
    const float* x     = (const float*)d_in[0];
    const float* cheby = (const float*)d_in[1];   // (8, 9, 4)
    const float* bw    = (const float*)d_in[2];   // (8, 9)
    const float* ss    = (const float*)d_in[3];   // (8, 9)
    float* out = (float*)d_out;

    cudaFuncSetAttribute(kan_conv_kernel,
                         cudaFuncAttributeMaxDynamicSharedMemorySize, SMEM_BYTES);

    kan_conv_kernel<<<GRID, NTHREADS, SMEM_BYTES>>>(x, cheby, bw, ss, out);
}

// round 11
// speedup vs baseline: 1.2330x; 1.2330x over previous
#include <cuda_runtime.h>

#define H 128
#define W 128
#define NCONV 8
#define TILE_ROWS 8
#define FROWS 10          // TILE_ROWS + 2 halo
#define ESTRIDE 66        // entries per (f,row) in Pe/Po (65/64 used, padded)
#define NTHREADS 256
#define NWARP 8
#define NTASK (FROWS * 5) // 50 feature tasks

// dynamic smem layout (bytes)
#define OFF_PE   0                                   // ull Pe[4][10][66] = 21120  (P[2m])
#define OFF_PO   21120                               // ull Po[4][10][66] = 21120  (P[2m+1])
#define OFF_W    42240                               // ull w[288]        = 2304
#define OFF_B    44544                               // ull bias[8]       = 64
#define SMEM_BYTES 44608

typedef unsigned long long ull;

__device__ __forceinline__ ull pk2(float lo, float hi) {
    ull r; asm("mov.b64 %0, {%1, %2};" : "=l"(r) : "f"(lo), "f"(hi)); return r;
}
__device__ __forceinline__ void fma2(ull &d, ull a, ull b) {
    asm("fma.rn.f32x2 %0, %1, %2, %0;" : "+l"(d) : "l"(a), "l"(b));
}
__device__ __forceinline__ float tanh_ap(float x) {
    float r; asm("tanh.approx.f32 %0, %1;" : "=f"(r) : "f"(x)); return r;
}

// features of one input value: 2 MUFU + a few fma
__device__ __forceinline__ void feats(float xv, float &s, float &t, float &t2, float &t3) {
    t = tanh_ap(xv);                               // tanh
    float th = tanh_ap(0.5f * xv);
    float sg = fmaf(0.5f, th, 0.5f);               // sigmoid(x)
    s  = xv * sg;                                  // silu
    t2 = fmaf(t + t, t, -1.f);                     // T2
    t3 = fmaf(t + t, t2, -t);                      // T3
}

__global__ void __launch_bounds__(NTHREADS, 4)
kan_conv_kernel(const float* __restrict__ x,
                const float* __restrict__ cheby,
                const float* __restrict__ bw,
                const float* __restrict__ ss,
                float* __restrict__ out)
{
    extern __shared__ char smem_raw[];
    ull* Pe    = (ull*)(smem_raw + OFF_PE);   // P[2m]   = (F(2m),   F(2m+1))
    ull* Po    = (ull*)(smem_raw + OFF_PO);   // P[2m+1] = (F(2m+1), F(2m+2))
    ull* wsm   = (ull*)(smem_raw + OFF_W);    // [(tap*4+f)*8 + j] dup pairs
    ull* biasd = (ull*)(smem_raw + OFF_B);

    const int tid  = threadIdx.x;
    const int wid  = tid >> 5;
    const int lane = tid & 31;
    const int blk  = blockIdx.x;
    const int bc   = blk >> 4;                    // plane b*C + c (0..255)
    const int r0   = (blk & 15) * TILE_ROWS;      // tile top row

    const float* xp = x + (size_t)bc * (H * W);

    // ---- Phase B1: prefetch all feature-input LDGs (MLP up to 7 per warp) ----
    // task = wid + 8q -> (row, chunk c) via increment-only mapping (no divisions):
    //   init: row = wid>=5, c = wid-5*row;  step(+8): row+=1, c+=3, carry if c>=5.
    float xv[7];
    {
        int row = (wid >= 5) ? 1 : 0;
        int c   = wid - ((wid >= 5) ? 5 : 0);
        #pragma unroll
        for (int q = 0; q < 7; q++) {
            int gr  = r0 - 1 + row;
            int col = ((c << 5) - c) + lane - 1;   // c*31 + lane - 1
            xv[q] = 0.f;
            if ((wid + q * 8 < NTASK) & ((unsigned)gr < H) & ((unsigned)col < W))
                xv[q] = xp[(gr << 7) + col];       // W == 128
            row += 1; c += 3;
            if (c >= 5) { c -= 5; row += 1; }
        }
    }

    // ---- Phase A: weights -> smem (covers the in-flight LDGs above) ----
    for (int idx = tid; idx < 9 * 4 * 8; idx += NTHREADS) {
        int j   = idx & 7;
        int fi  = idx >> 3;
        int tap = fi >> 2;
        int f   = fi & 3;
        float wv;
        if (f == 0) wv = bw[j * 9 + tap];
        else        wv = cheby[(j * 9 + tap) * 4 + f] * ss[j * 9 + tap];
        wsm[idx] = pk2(wv, wv);
    }
    if (tid < NCONV) {
        float sum = 0.f;
        #pragma unroll
        for (int i = 0; i < 9; i++) sum += cheby[(tid * 9 + i) * 4] * ss[tid * 9 + i];
        biasd[tid] = pk2(sum, sum);
    }

    // ---- Phase B2: features -> parity-split pair smem, conflict-free ----
    {
        int c    = wid - ((wid >= 5) ? 5 : 0);
        int rowE = (wid >= 5) ? ESTRIDE : 0;       // row * ESTRIDE, maintained incrementally
        #pragma unroll
        for (int q = 0; q < 7; q++) {
            if (wid + q * 8 < NTASK) {             // warp-uniform (only q=6 is a real test)
                int i = ((c << 5) - c) + lane;     // feature index (col = i-1)
                float s, t1, t2, t3;
                feats(xv[q], s, t1, t2, t3);       // x=0 padding -> (0,0,-1,0) ✓
                float ps  = __shfl_up_sync(0xffffffffu, s,  1);
                float pt  = __shfl_up_sync(0xffffffffu, t1, 1);
                float pt2 = __shfl_up_sync(0xffffffffu, t2, 1);
                float pt3 = __shfl_up_sync(0xffffffffu, t3, 1);
                int k = i - 1;
                if (lane >= 1 && k <= 128) {
                    int rb = rowE + (k >> 1);
                    ull v0 = pk2(ps,  s);
                    ull v1 = pk2(pt,  t1);
                    ull v2 = pk2(pt2, t2);
                    ull v3 = pk2(pt3, t3);
                    if ((k & 1) == 0) {
                        Pe[(0 * FROWS) * ESTRIDE + rb] = v0;
                        Pe[(1 * FROWS) * ESTRIDE + rb] = v1;
                        Pe[(2 * FROWS) * ESTRIDE + rb] = v2;
                        Pe[(3 * FROWS) * ESTRIDE + rb] = v3;
                    } else {
                        Po[(0 * FROWS) * ESTRIDE + rb] = v0;
                        Po[(1 * FROWS) * ESTRIDE + rb] = v1;
                        Po[(2 * FROWS) * ESTRIDE + rb] = v2;
                        Po[(3 * FROWS) * ESTRIDE + rb] = v3;
                    }
                }
            }
            c += 3;
            if (c >= 5) { c -= 5; rowE += 2 * ESTRIDE; } else { rowE += ESTRIDE; }
        }
    }
    __syncthreads();

    // ---- Compute: thread -> 2 output rows (ty, ty+1), cols {2L, 2L+1}, 8 j ----
    // Rolling 2-row feature window keeps live regs <= 64 at 2-row amortization.
    const int L  = tid & 63;                       // col-pair index, c0 = 2L
    const int ty = (tid >> 6) * 2;                 // local out rows ty, ty+1

    ull acc[8][2];                                 // [j][r]
    #pragma unroll
    for (int j = 0; j < 8; j++) {
        ull b = biasd[j];
        acc[j][0] = b; acc[j][1] = b;
    }

    const int tybase = ty * ESTRIDE + L;           // single IMAD; rest are immediates

    #pragma unroll
    for (int f = 0; f < 4; f++) {
        ull lo[3], hi[3];
        {   // input rows ty (lo) and ty+1 (hi)
            int b0 = (f * FROWS) * ESTRIDE + tybase;
            lo[0] = Pe[b0]; lo[1] = Po[b0]; lo[2] = Pe[b0 + 1];
            int b1 = b0 + ESTRIDE;
            hi[0] = Pe[b1]; hi[1] = Po[b1]; hi[2] = Pe[b1 + 1];
        }
        #pragma unroll
        for (int dy = 0; dy < 3; dy++) {
            #pragma unroll
            for (int dx = 0; dx < 3; dx++) {
                const ulonglong2* wp = (const ulonglong2*)&wsm[((dy * 3 + dx) * 4 + f) * 8];
                ull f0 = lo[dx];                   // feeds out row ty
                ull f1 = hi[dx];                   // feeds out row ty+1
                {   // j 0..3
                    ulonglong2 w01 = wp[0], w23 = wp[1];
                    fma2(acc[0][0], f0, w01.x); fma2(acc[0][1], f1, w01.x);
                    fma2(acc[1][0], f0, w01.y); fma2(acc[1][1], f1, w01.y);
                    fma2(acc[2][0], f0, w23.x); fma2(acc[2][1], f1, w23.x);
                    fma2(acc[3][0], f0, w23.y); fma2(acc[3][1], f1, w23.y);
                }
                {   // j 4..7
                    ulonglong2 w45 = wp[2], w67 = wp[3];
                    fma2(acc[4][0], f0, w45.x); fma2(acc[4][1], f1, w45.x);
                    fma2(acc[5][0], f0, w45.y); fma2(acc[5][1], f1, w45.y);
                    fma2(acc[6][0], f0, w67.x); fma2(acc[6][1], f1, w67.x);
                    fma2(acc[7][0], f0, w67.y); fma2(acc[7][1], f1, w67.y);
                }
            }
            if (dy < 2) {                          // roll window: lo <- hi, load next row
                lo[0] = hi[0]; lo[1] = hi[1]; lo[2] = hi[2];
                int bn = (f * FROWS + dy + 2) * ESTRIDE + tybase;
                hi[0] = Pe[bn]; hi[1] = Po[bn]; hi[2] = Pe[bn + 1];
            }
        }
    }

    // ---- stores: STG.64, dense per warp ----
    float* ob = out + ((size_t)(bc * NCONV) * H + (r0 + ty)) * W + 2 * L;
    #pragma unroll
    for (int j = 0; j < 8; j++) {
        #pragma unroll
        for (int r = 0; r < 2; r++) {
            *(ull*)(ob + (size_t)j * (H * W) + r * W) = acc[j][r];
        }
    }
}

extern "C" void kernel_launch(void* const* d_in, const int* in_sizes, int n_in,
                              void* d_out, int out_size) {
    const float* x     = (const float*)d_in[0];
    const float* cheby = (const float*)d_in[1];   // (8, 9, 4)
    const float* bw    = (const float*)d_in[2];   // (8, 9)
    const float* ss    = (const float*)d_in[3];   // (8, 9)
    float* out = (float*)d_out;

    cudaFuncSetAttribute(kan_conv_kernel,
                         cudaFuncAttributeMaxDynamicSharedMemorySize, SMEM_BYTES);

    const int planes = 16 * 16;                   // B * C
    dim3 grid(planes * (H / TILE_ROWS));          // 4096 blocks
    kan_conv_kernel<<<grid, NTHREADS, SMEM_BYTES>>>(x, cheby, bw, ss, out);
}